// round 8
// baseline (speedup 1.0000x reference)
#include <cuda_runtime.h>
#include <math.h>
#include <stdint.h>

// Problem constants (fixed by setup_inputs)
#define B_   4
#define S_   1024
#define D_   768
#define H_   12
#define HD_  64
#define F_   3072
#define L_   6
#define D3_  2304
#define BH_  (B_ * H_)
#define MTOK (B_ * S_)   // 4096 token rows

// ---------------------------------------------------------------------------
// Scratch (static device globals; no allocation anywhere)
// ---------------------------------------------------------------------------
__device__ float g_h   [(size_t)MTOK * D_];     // hidden state
__device__ float g_tmp [(size_t)MTOK * D_];     // pre-LN sums
__device__ float g_attn[(size_t)MTOK * D_];     // attention output (B,S,D)
__device__ float g_qkv [(size_t)MTOK * D3_];    // fused qkv (q|k|v per token)
__device__ float g_sc  [(size_t)BH_ * S_ * S_]; // scores / weights
__device__ float g_ffn [(size_t)MTOK * F_];     // FFN intermediate

// ---------------------------------------------------------------------------
// Helpers
// ---------------------------------------------------------------------------
__device__ __forceinline__ float to_tf32(float x) {
    uint32_t u;
    asm("cvt.rna.tf32.f32 %0, %1;" : "=r"(u) : "f"(x));
    return __uint_as_float(u);
}

// D += A(16x8, tf32, row) * B(8x8, tf32, col)
__device__ __forceinline__ void mma8(float* c, const uint32_t* a, const uint32_t* b) {
    asm volatile(
        "mma.sync.aligned.m16n8k8.row.col.f32.tf32.tf32.f32 "
        "{%0,%1,%2,%3}, {%4,%5,%6,%7}, {%8,%9}, {%0,%1,%2,%3};\n"
        : "+f"(c[0]), "+f"(c[1]), "+f"(c[2]), "+f"(c[3])
        : "r"(a[0]), "r"(a[1]), "r"(a[2]), "r"(a[3]), "r"(b[0]), "r"(b[1]));
}

__device__ __forceinline__ float warp_max(float v) {
#pragma unroll
    for (int o = 16; o > 0; o >>= 1) v = fmaxf(v, __shfl_xor_sync(0xffffffffu, v, o));
    return v;
}
__device__ __forceinline__ float warp_sum(float v) {
#pragma unroll
    for (int o = 16; o > 0; o >>= 1) v += __shfl_xor_sync(0xffffffffu, v, o);
    return v;
}

// ---------------------------------------------------------------------------
// 1) x + positional encoding
// ---------------------------------------------------------------------------
__global__ void pos_add_kernel(const float* __restrict__ x, float* __restrict__ out) {
    int t = blockIdx.x * blockDim.x + threadIdx.x;
    if (t >= MTOK * D_) return;
    int d = t % D_;
    int s = (t / D_) % S_;
    int i2 = d & ~1;
    float f = expf((float)i2 * (-9.210340371976184f / (float)D_)); // -log(1e4)/D
    float ang = (float)s * f;
    float pe = (d & 1) ? cosf(ang) : sinf(ang);
    out[t] = x[t] + pe;
}

// ---------------------------------------------------------------------------
// 2) Dense TF32 tensor-core GEMM: C = A[M,K] @ B[K,N] (+bias)(+relu)(+resid)
//    CTA tile 128x128x32, 8 warps (2x4), warp tile 64x32, m16n8k8 tf32 mma.
// ---------------------------------------------------------------------------
template<bool RELU, bool RESID>
__global__ void __launch_bounds__(256)
gemm_tf32(const float* __restrict__ A, const float* __restrict__ Bm,
          const float* __restrict__ bias, const float* __restrict__ R,
          float* __restrict__ C, int K, int N)
{
    __shared__ float As[32][132];   // [k][m], stride 132 => conflict-free frags
    __shared__ float Bs[32][132];   // [k][n]

    const int tid  = threadIdx.x;
    const int warp = tid >> 5, lane = tid & 31;
    const int grp  = lane >> 2, qd = lane & 3;
    const int wm   = (warp >> 2) * 64;   // 0 / 64
    const int wn   = (warp & 3)  * 32;   // 0..96

    const float* Ab = A  + (long)blockIdx.y * 128 * K;
    const float* Bb = Bm + blockIdx.x * 128;

    const int am = tid >> 1;            // 0..127
    const int ak = (tid & 1) * 4;       // 0 / 4
    const int bk = tid >> 5;            // 0..7
    const int bn = (tid & 31) * 4;      // 0..124

    float acc[4][4][4] = {};

    for (int k0 = 0; k0 < K; k0 += 32) {
        const float* pa = Ab + (long)am * K + k0 + ak;
#pragma unroll
        for (int kk = 0; kk < 32; kk += 8) {
            float4 v = *(const float4*)(pa + kk);
            As[ak + kk + 0][am] = to_tf32(v.x);
            As[ak + kk + 1][am] = to_tf32(v.y);
            As[ak + kk + 2][am] = to_tf32(v.z);
            As[ak + kk + 3][am] = to_tf32(v.w);
        }
#pragma unroll
        for (int kk = 0; kk < 32; kk += 8) {
            float4 v = *(const float4*)(Bb + (long)(k0 + bk + kk) * N + bn);
            v.x = to_tf32(v.x); v.y = to_tf32(v.y);
            v.z = to_tf32(v.z); v.w = to_tf32(v.w);
            *(float4*)(&Bs[bk + kk][bn]) = v;
        }
        __syncthreads();

#pragma unroll
        for (int ks = 0; ks < 4; ks++) {
            const int kb = ks * 8;
            uint32_t a[4][4], b[4][2];
#pragma unroll
            for (int i = 0; i < 4; i++) {
                int m = wm + i * 16 + grp;
                a[i][0] = __float_as_uint(As[kb + qd    ][m]);
                a[i][1] = __float_as_uint(As[kb + qd    ][m + 8]);
                a[i][2] = __float_as_uint(As[kb + qd + 4][m]);
                a[i][3] = __float_as_uint(As[kb + qd + 4][m + 8]);
            }
#pragma unroll
            for (int j = 0; j < 4; j++) {
                int n = wn + j * 8 + grp;
                b[j][0] = __float_as_uint(Bs[kb + qd    ][n]);
                b[j][1] = __float_as_uint(Bs[kb + qd + 4][n]);
            }
#pragma unroll
            for (int i = 0; i < 4; i++)
#pragma unroll
                for (int j = 0; j < 4; j++)
                    mma8(acc[i][j], a[i], b[j]);
        }
        __syncthreads();
    }

    const int row0 = blockIdx.y * 128 + wm + grp;
    const int col0 = blockIdx.x * 128 + wn + qd * 2;
#pragma unroll
    for (int i = 0; i < 4; i++) {
#pragma unroll
        for (int j = 0; j < 4; j++) {
            int r  = row0 + i * 16;
            int cc = col0 + j * 8;
            float2 v0 = make_float2(acc[i][j][0], acc[i][j][1]);
            float2 v1 = make_float2(acc[i][j][2], acc[i][j][3]);
            if (bias) {
                float b0 = bias[cc], b1 = bias[cc + 1];
                v0.x += b0; v0.y += b1; v1.x += b0; v1.y += b1;
            }
            if (RELU) {
                v0.x = fmaxf(v0.x, 0.f); v0.y = fmaxf(v0.y, 0.f);
                v1.x = fmaxf(v1.x, 0.f); v1.y = fmaxf(v1.y, 0.f);
            }
            long o0 = (long)r * N + cc;
            long o1 = (long)(r + 8) * N + cc;
            if (RESID) {
                float2 r0 = *(const float2*)(R + o0);
                float2 r1 = *(const float2*)(R + o1);
                v0.x += r0.x; v0.y += r0.y; v1.x += r1.x; v1.y += r1.y;
            }
            *(float2*)(C + o0) = v0;
            *(float2*)(C + o1) = v1;
        }
    }
}

// ---------------------------------------------------------------------------
// 3) QK^T: scores[bh, q, k] = 0.125 * sum_d Q[q][d] K[k][d]
//    Q, K read directly out of fused qkv (K is naturally col-major for row.col).
// ---------------------------------------------------------------------------
__global__ void __launch_bounds__(256)
qk_tf32(const float* __restrict__ qkv, float* __restrict__ sc)
{
    __shared__ float As[32][132];   // [d][q]
    __shared__ float Bs[32][132];   // [d][k_tok]

    const int tid  = threadIdx.x;
    const int warp = tid >> 5, lane = tid & 31;
    const int grp  = lane >> 2, qd = lane & 3;
    const int wm   = (warp >> 2) * 64;
    const int wn   = (warp & 3)  * 32;

    const int bh = blockIdx.z;
    const int b = bh / H_, h = bh % H_;
    const float* Qb = qkv + (long)b * S_ * D3_ + h * HD_        + (long)blockIdx.y * 128 * D3_;
    const float* Kb = qkv + (long)b * S_ * D3_ + D_ + h * HD_   + (long)blockIdx.x * 128 * D3_;

    const int am = tid >> 1;
    const int ak = (tid & 1) * 4;

    float acc[4][4][4] = {};

    for (int k0 = 0; k0 < HD_; k0 += 32) {
        const float* pa = Qb + (long)am * D3_ + k0 + ak;
        const float* pb = Kb + (long)am * D3_ + k0 + ak;
#pragma unroll
        for (int kk = 0; kk < 32; kk += 8) {
            float4 va = *(const float4*)(pa + kk);
            As[ak + kk + 0][am] = to_tf32(va.x);
            As[ak + kk + 1][am] = to_tf32(va.y);
            As[ak + kk + 2][am] = to_tf32(va.z);
            As[ak + kk + 3][am] = to_tf32(va.w);
            float4 vb = *(const float4*)(pb + kk);
            Bs[ak + kk + 0][am] = to_tf32(vb.x);
            Bs[ak + kk + 1][am] = to_tf32(vb.y);
            Bs[ak + kk + 2][am] = to_tf32(vb.z);
            Bs[ak + kk + 3][am] = to_tf32(vb.w);
        }
        __syncthreads();

#pragma unroll
        for (int ks = 0; ks < 4; ks++) {
            const int kb = ks * 8;
            uint32_t a[4][4], b2[4][2];
#pragma unroll
            for (int i = 0; i < 4; i++) {
                int m = wm + i * 16 + grp;
                a[i][0] = __float_as_uint(As[kb + qd    ][m]);
                a[i][1] = __float_as_uint(As[kb + qd    ][m + 8]);
                a[i][2] = __float_as_uint(As[kb + qd + 4][m]);
                a[i][3] = __float_as_uint(As[kb + qd + 4][m + 8]);
            }
#pragma unroll
            for (int j = 0; j < 4; j++) {
                int n = wn + j * 8 + grp;
                b2[j][0] = __float_as_uint(Bs[kb + qd    ][n]);
                b2[j][1] = __float_as_uint(Bs[kb + qd + 4][n]);
            }
#pragma unroll
            for (int i = 0; i < 4; i++)
#pragma unroll
                for (int j = 0; j < 4; j++)
                    mma8(acc[i][j], a[i], b2[j]);
        }
        __syncthreads();
    }

    float* Cb = sc + (long)bh * S_ * S_;
    const int row0 = blockIdx.y * 128 + wm + grp;
    const int col0 = blockIdx.x * 128 + wn + qd * 2;
#pragma unroll
    for (int i = 0; i < 4; i++)
#pragma unroll
        for (int j = 0; j < 4; j++) {
            int r  = row0 + i * 16;
            int cc = col0 + j * 8;
            *(float2*)(Cb + (long)r * S_ + cc) =
                make_float2(acc[i][j][0] * 0.125f, acc[i][j][1] * 0.125f);
            *(float2*)(Cb + (long)(r + 8) * S_ + cc) =
                make_float2(acc[i][j][2] * 0.125f, acc[i][j][3] * 0.125f);
        }
}

// ---------------------------------------------------------------------------
// 4) Row softmax + clip(1e-6, 1.0), in-place, row length 1024
// ---------------------------------------------------------------------------
__global__ void __launch_bounds__(256)
softmax_clamp_kernel(float* __restrict__ sc)
{
    float* p = sc + (long)blockIdx.x * S_;
    int tid = threadIdx.x, wid = tid >> 5, lane = tid & 31;
    __shared__ float sred[8];
    __shared__ float sbc[2];

    float4 v = ((float4*)p)[tid];
    float m = fmaxf(fmaxf(v.x, v.y), fmaxf(v.z, v.w));
    m = warp_max(m);
    if (lane == 0) sred[wid] = m;
    __syncthreads();
    if (wid == 0) {
        float t = (lane < 8) ? sred[lane] : -INFINITY;
        t = warp_max(t);
        if (lane == 0) sbc[0] = t;
    }
    __syncthreads();
    float rowmax = sbc[0];

    float4 e;
    e.x = expf(v.x - rowmax);
    e.y = expf(v.y - rowmax);
    e.z = expf(v.z - rowmax);
    e.w = expf(v.w - rowmax);
    float s = e.x + e.y + e.z + e.w;
    s = warp_sum(s);
    if (lane == 0) sred[wid] = s;
    __syncthreads();
    if (wid == 0) {
        float t = (lane < 8) ? sred[lane] : 0.0f;
        t = warp_sum(t);
        if (lane == 0) sbc[1] = t;
    }
    __syncthreads();
    float inv = 1.0f / sbc[1];

    e.x = fminf(fmaxf(e.x * inv, 1e-6f), 1.0f);
    e.y = fminf(fmaxf(e.y * inv, 1e-6f), 1.0f);
    e.z = fminf(fmaxf(e.z * inv, 1e-6f), 1.0f);
    e.w = fminf(fmaxf(e.w * inv, 1e-6f), 1.0f);
    ((float4*)p)[tid] = e;
}

// ---------------------------------------------------------------------------
// 5) PV: attn[b, s, h*64+d] = sum_k W[bh,s,k] * V[bh,k,d]
//    TF32 mma, CTA tile 128x64x32, warp tile 32x32 (4x2 warps).
//    V read directly from fused qkv; output written in (B,S,D) layout.
// ---------------------------------------------------------------------------
__global__ void __launch_bounds__(256)
pv_tf32(const float* __restrict__ sc, const float* __restrict__ qkv,
        float* __restrict__ attn)
{
    __shared__ float As[32][132];   // [k][s]
    __shared__ float Bs[32][68];    // [k][d]

    const int tid  = threadIdx.x;
    const int warp = tid >> 5, lane = tid & 31;
    const int grp  = lane >> 2, qd = lane & 3;
    const int wm   = (warp >> 1) * 32;  // 0,32,64,96
    const int wn   = (warp & 1)  * 32;  // 0,32

    const int bh = blockIdx.z;
    const int b = bh / H_, h = bh % H_;
    const float* Ab = sc  + (long)bh * S_ * S_ + (long)blockIdx.y * 128 * S_;
    const float* Vb = qkv + (long)b * S_ * D3_ + 2 * D_ + h * HD_;
    float*       Cb = attn + (long)b * S_ * D_ + h * HD_ + (long)blockIdx.y * 128 * D_;

    const int am = tid >> 1;
    const int ak = (tid & 1) * 4;
    const int bk = tid >> 4;            // 0..15
    const int bn = (tid & 15) * 4;      // 0..60

    float acc[2][4][4] = {};

    for (int k0 = 0; k0 < S_; k0 += 32) {
        const float* pa = Ab + (long)am * S_ + k0 + ak;
#pragma unroll
        for (int kk = 0; kk < 32; kk += 8) {
            float4 v = *(const float4*)(pa + kk);
            As[ak + kk + 0][am] = to_tf32(v.x);
            As[ak + kk + 1][am] = to_tf32(v.y);
            As[ak + kk + 2][am] = to_tf32(v.z);
            As[ak + kk + 3][am] = to_tf32(v.w);
        }
#pragma unroll
        for (int kk = 0; kk < 32; kk += 16) {
            float4 v = *(const float4*)(Vb + (long)(k0 + bk + kk) * D3_ + bn);
            v.x = to_tf32(v.x); v.y = to_tf32(v.y);
            v.z = to_tf32(v.z); v.w = to_tf32(v.w);
            *(float4*)(&Bs[bk + kk][bn]) = v;
        }
        __syncthreads();

#pragma unroll
        for (int ks = 0; ks < 4; ks++) {
            const int kb = ks * 8;
            uint32_t a[2][4], b2[4][2];
#pragma unroll
            for (int i = 0; i < 2; i++) {
                int m = wm + i * 16 + grp;
                a[i][0] = __float_as_uint(As[kb + qd    ][m]);
                a[i][1] = __float_as_uint(As[kb + qd    ][m + 8]);
                a[i][2] = __float_as_uint(As[kb + qd + 4][m]);
                a[i][3] = __float_as_uint(As[kb + qd + 4][m + 8]);
            }
#pragma unroll
            for (int j = 0; j < 4; j++) {
                int n = wn + j * 8 + grp;
                b2[j][0] = __float_as_uint(Bs[kb + qd    ][n]);
                b2[j][1] = __float_as_uint(Bs[kb + qd + 4][n]);
            }
#pragma unroll
            for (int i = 0; i < 2; i++)
#pragma unroll
                for (int j = 0; j < 4; j++)
                    mma8(acc[i][j], a[i], b2[j]);
        }
        __syncthreads();
    }

    const int row0 = wm + grp;
    const int col0 = wn + qd * 2;
#pragma unroll
    for (int i = 0; i < 2; i++)
#pragma unroll
        for (int j = 0; j < 4; j++) {
            int r  = row0 + i * 16;
            int cc = col0 + j * 8;
            *(float2*)(Cb + (long)r * D_ + cc) =
                make_float2(acc[i][j][0], acc[i][j][1]);
            *(float2*)(Cb + (long)(r + 8) * D_ + cc) =
                make_float2(acc[i][j][2], acc[i][j][3]);
        }
}

// ---------------------------------------------------------------------------
// 6) LayerNorm (row length 768)
// ---------------------------------------------------------------------------
__global__ void __launch_bounds__(256)
layernorm_kernel(const float* __restrict__ in, const float* __restrict__ g,
                 const float* __restrict__ bb, float* __restrict__ out)
{
    const float* p = in + (long)blockIdx.x * D_;
    float* o = out + (long)blockIdx.x * D_;
    int tid = threadIdx.x, wid = tid >> 5, lane = tid & 31;

    float x0 = p[tid], x1 = p[tid + 256], x2 = p[tid + 512];
    float s  = x0 + x1 + x2;
    float s2 = x0 * x0 + x1 * x1 + x2 * x2;
    s  = warp_sum(s);
    s2 = warp_sum(s2);

    __shared__ float red[16];
    if (lane == 0) { red[wid] = s; red[8 + wid] = s2; }
    __syncthreads();
    if (tid == 0) {
        float a = 0.f, b2 = 0.f;
#pragma unroll
        for (int i = 0; i < 8; i++) { a += red[i]; b2 += red[8 + i]; }
        red[0] = a; red[8] = b2;
    }
    __syncthreads();
    float mu  = red[0] * (1.0f / (float)D_);
    float var = red[8] * (1.0f / (float)D_) - mu * mu;
    float inv = rsqrtf(var + 1e-5f);

    o[tid]       = (x0 - mu) * inv * g[tid]       + bb[tid];
    o[tid + 256] = (x1 - mu) * inv * g[tid + 256] + bb[tid + 256];
    o[tid + 512] = (x2 - mu) * inv * g[tid + 512] + bb[tid + 512];
}

// ---------------------------------------------------------------------------
// Orchestration
// ---------------------------------------------------------------------------
extern "C" void kernel_launch(void* const* d_in, const int* in_sizes, int n_in,
                              void* d_out, int out_size)
{
    (void)in_sizes; (void)n_in; (void)out_size;

    const float* x    = (const float*)d_in[0];
    const float* Wqkv = (const float*)d_in[1];
    const float* bqkv = (const float*)d_in[2];
    const float* Wo   = (const float*)d_in[3];
    const float* bo   = (const float*)d_in[4];
    const float* ln1g = (const float*)d_in[5];
    const float* ln1b = (const float*)d_in[6];
    const float* W1   = (const float*)d_in[7];
    const float* b1   = (const float*)d_in[8];
    const float* W2   = (const float*)d_in[9];
    const float* b2   = (const float*)d_in[10];
    const float* ln2g = (const float*)d_in[11];
    const float* ln2b = (const float*)d_in[12];
    const float* lnfg = (const float*)d_in[13];
    const float* lnfb = (const float*)d_in[14];

    float *p_h, *p_tmp, *p_attn, *p_qkv, *p_sc, *p_ffn;
    cudaGetSymbolAddress((void**)&p_h,    g_h);
    cudaGetSymbolAddress((void**)&p_tmp,  g_tmp);
    cudaGetSymbolAddress((void**)&p_attn, g_attn);
    cudaGetSymbolAddress((void**)&p_qkv,  g_qkv);
    cudaGetSymbolAddress((void**)&p_sc,   g_sc);
    cudaGetSymbolAddress((void**)&p_ffn,  g_ffn);

    const int elems = MTOK * D_;

    pos_add_kernel<<<elems / 256, 256>>>(x, p_h);

    for (int l = 0; l < L_; l++) {
        const float* wqkv = Wqkv + (size_t)l * D_ * D3_;
        const float* bq   = bqkv + (size_t)l * D3_;
        const float* wo   = Wo   + (size_t)l * D_ * D_;
        const float* bol  = bo   + (size_t)l * D_;
        const float* w1   = W1   + (size_t)l * D_ * F_;
        const float* b1l  = b1   + (size_t)l * F_;
        const float* w2   = W2   + (size_t)l * F_ * D_;
        const float* b2l  = b2   + (size_t)l * D_;

        // qkv = h @ Wqkv + bqkv              (4096 x 2304 x 768)
        gemm_tf32<false, false><<<dim3(D3_ / 128, MTOK / 128), 256>>>(
            p_h, wqkv, bq, nullptr, p_qkv, D_, D3_);

        // scores = 0.125 * Q @ K^T           (batched 1024 x 1024 x 64)
        qk_tf32<<<dim3(S_ / 128, S_ / 128, BH_), 256>>>(p_qkv, p_sc);

        // softmax + clamp
        softmax_clamp_kernel<<<BH_ * S_, 256>>>(p_sc);

        // attn = W @ V                       (batched 1024 x 64 x 1024)
        pv_tf32<<<dim3(1, S_ / 128, BH_), 256>>>(p_sc, p_qkv, p_attn);

        // tmp = attn @ Wo + bo + h           (4096 x 768 x 768)
        gemm_tf32<false, true><<<dim3(D_ / 128, MTOK / 128), 256>>>(
            p_attn, wo, bol, p_h, p_tmp, D_, D_);

        layernorm_kernel<<<MTOK, 256>>>(p_tmp, ln1g + (size_t)l * D_,
                                        ln1b + (size_t)l * D_, p_h);

        // ffn = relu(h @ W1 + b1)            (4096 x 3072 x 768)
        gemm_tf32<true, false><<<dim3(F_ / 128, MTOK / 128), 256>>>(
            p_h, w1, b1l, nullptr, p_ffn, D_, F_);

        // tmp = ffn @ W2 + b2 + h            (4096 x 768 x 3072)
        gemm_tf32<false, true><<<dim3(D_ / 128, MTOK / 128), 256>>>(
            p_ffn, w2, b2l, p_h, p_tmp, F_, D_);

        layernorm_kernel<<<MTOK, 256>>>(p_tmp, ln2g + (size_t)l * D_,
                                        ln2b + (size_t)l * D_, p_h);
    }

    layernorm_kernel<<<MTOK, 256>>>(p_h, lnfg, lnfb, (float*)d_out);
}

// round 11
// speedup vs baseline: 1.0018x; 1.0018x over previous
#include <cuda_runtime.h>
#include <math.h>
#include <stdint.h>

// Problem constants (fixed by setup_inputs)
#define B_   4
#define S_   1024
#define D_   768
#define H_   12
#define HD_  64
#define F_   3072
#define L_   6
#define D3_  2304
#define BH_  (B_ * H_)
#define MTOK (B_ * S_)   // 4096 token rows

// ---------------------------------------------------------------------------
// Scratch (static device globals; no allocation anywhere)
// ---------------------------------------------------------------------------
__device__ float g_h   [(size_t)MTOK * D_];     // hidden state
__device__ float g_tmp [(size_t)MTOK * D_];     // pre-LN sums
__device__ float g_attn[(size_t)MTOK * D_];     // attention output (B,S,D)
__device__ float g_qkv [(size_t)MTOK * D3_];    // fused qkv (q|k|v per token)
__device__ float g_sc  [(size_t)BH_ * S_ * S_]; // scores / weights
__device__ float g_ffn [(size_t)MTOK * F_];     // FFN intermediate

// ---------------------------------------------------------------------------
// Helpers
// ---------------------------------------------------------------------------
__device__ __forceinline__ float to_tf32(float x) {
    uint32_t u;
    asm("cvt.rna.tf32.f32 %0, %1;" : "=r"(u) : "f"(x));
    return __uint_as_float(u);
}

// D += A(16x8, tf32, row) * B(8x8, tf32, col)
__device__ __forceinline__ void mma8(float* c, const uint32_t* a, const uint32_t* b) {
    asm volatile(
        "mma.sync.aligned.m16n8k8.row.col.f32.tf32.tf32.f32 "
        "{%0,%1,%2,%3}, {%4,%5,%6,%7}, {%8,%9}, {%0,%1,%2,%3};\n"
        : "+f"(c[0]), "+f"(c[1]), "+f"(c[2]), "+f"(c[3])
        : "r"(a[0]), "r"(a[1]), "r"(a[2]), "r"(a[3]), "r"(b[0]), "r"(b[1]));
}

__device__ __forceinline__ float warp_max(float v) {
#pragma unroll
    for (int o = 16; o > 0; o >>= 1) v = fmaxf(v, __shfl_xor_sync(0xffffffffu, v, o));
    return v;
}
__device__ __forceinline__ float warp_sum(float v) {
#pragma unroll
    for (int o = 16; o > 0; o >>= 1) v += __shfl_xor_sync(0xffffffffu, v, o);
    return v;
}

// ---------------------------------------------------------------------------
// 1) x + positional encoding
// ---------------------------------------------------------------------------
__global__ void pos_add_kernel(const float* __restrict__ x, float* __restrict__ out) {
    int t = blockIdx.x * blockDim.x + threadIdx.x;
    if (t >= MTOK * D_) return;
    int d = t % D_;
    int s = (t / D_) % S_;
    int i2 = d & ~1;
    float f = expf((float)i2 * (-9.210340371976184f / (float)D_)); // -log(1e4)/D
    float ang = (float)s * f;
    float pe = (d & 1) ? cosf(ang) : sinf(ang);
    out[t] = x[t] + pe;
}

// ---------------------------------------------------------------------------
// 2) Dense TF32 tensor-core GEMM: C = A[M,K] @ B[K,N] (+bias)(+relu)(+resid)
//    CTA tile 128x128x32, 8 warps (2x4), warp tile 64x32, m16n8k8 tf32 mma.
// ---------------------------------------------------------------------------
template<bool RELU, bool RESID>
__global__ void __launch_bounds__(256)
gemm_tf32(const float* __restrict__ A, const float* __restrict__ Bm,
          const float* __restrict__ bias, const float* __restrict__ R,
          float* __restrict__ C, int K, int N)
{
    __shared__ float As[32][132];   // [k][m], stride 132 => conflict-free frags
    __shared__ float Bs[32][132];   // [k][n]

    const int tid  = threadIdx.x;
    const int warp = tid >> 5, lane = tid & 31;
    const int grp  = lane >> 2, qd = lane & 3;
    const int wm   = (warp >> 2) * 64;   // 0 / 64
    const int wn   = (warp & 3)  * 32;   // 0..96

    const float* Ab = A  + (long)blockIdx.y * 128 * K;
    const float* Bb = Bm + blockIdx.x * 128;

    const int am = tid >> 1;            // 0..127
    const int ak = (tid & 1) * 4;       // 0 / 4
    const int bk = tid >> 5;            // 0..7
    const int bn = (tid & 31) * 4;      // 0..124

    float acc[4][4][4] = {};

    for (int k0 = 0; k0 < K; k0 += 32) {
        const float* pa = Ab + (long)am * K + k0 + ak;
#pragma unroll
        for (int kk = 0; kk < 32; kk += 8) {
            float4 v = *(const float4*)(pa + kk);
            As[ak + kk + 0][am] = to_tf32(v.x);
            As[ak + kk + 1][am] = to_tf32(v.y);
            As[ak + kk + 2][am] = to_tf32(v.z);
            As[ak + kk + 3][am] = to_tf32(v.w);
        }
#pragma unroll
        for (int kk = 0; kk < 32; kk += 8) {
            float4 v = *(const float4*)(Bb + (long)(k0 + bk + kk) * N + bn);
            v.x = to_tf32(v.x); v.y = to_tf32(v.y);
            v.z = to_tf32(v.z); v.w = to_tf32(v.w);
            *(float4*)(&Bs[bk + kk][bn]) = v;
        }
        __syncthreads();

#pragma unroll
        for (int ks = 0; ks < 4; ks++) {
            const int kb = ks * 8;
            uint32_t a[4][4], b[4][2];
#pragma unroll
            for (int i = 0; i < 4; i++) {
                int m = wm + i * 16 + grp;
                a[i][0] = __float_as_uint(As[kb + qd    ][m]);
                a[i][1] = __float_as_uint(As[kb + qd    ][m + 8]);
                a[i][2] = __float_as_uint(As[kb + qd + 4][m]);
                a[i][3] = __float_as_uint(As[kb + qd + 4][m + 8]);
            }
#pragma unroll
            for (int j = 0; j < 4; j++) {
                int n = wn + j * 8 + grp;
                b[j][0] = __float_as_uint(Bs[kb + qd    ][n]);
                b[j][1] = __float_as_uint(Bs[kb + qd + 4][n]);
            }
#pragma unroll
            for (int i = 0; i < 4; i++)
#pragma unroll
                for (int j = 0; j < 4; j++)
                    mma8(acc[i][j], a[i], b[j]);
        }
        __syncthreads();
    }

    const int row0 = blockIdx.y * 128 + wm + grp;
    const int col0 = blockIdx.x * 128 + wn + qd * 2;
#pragma unroll
    for (int i = 0; i < 4; i++) {
#pragma unroll
        for (int j = 0; j < 4; j++) {
            int r  = row0 + i * 16;
            int cc = col0 + j * 8;
            float2 v0 = make_float2(acc[i][j][0], acc[i][j][1]);
            float2 v1 = make_float2(acc[i][j][2], acc[i][j][3]);
            if (bias) {
                float b0 = bias[cc], b1 = bias[cc + 1];
                v0.x += b0; v0.y += b1; v1.x += b0; v1.y += b1;
            }
            if (RELU) {
                v0.x = fmaxf(v0.x, 0.f); v0.y = fmaxf(v0.y, 0.f);
                v1.x = fmaxf(v1.x, 0.f); v1.y = fmaxf(v1.y, 0.f);
            }
            long o0 = (long)r * N + cc;
            long o1 = (long)(r + 8) * N + cc;
            if (RESID) {
                float2 r0 = *(const float2*)(R + o0);
                float2 r1 = *(const float2*)(R + o1);
                v0.x += r0.x; v0.y += r0.y; v1.x += r1.x; v1.y += r1.y;
            }
            *(float2*)(C + o0) = v0;
            *(float2*)(C + o1) = v1;
        }
    }
}

// ---------------------------------------------------------------------------
// 3) QK^T: scores[bh, q, k] = 0.125 * sum_d Q[q][d] K[k][d]
//    Q, K read directly out of fused qkv (K is naturally col-major for row.col).
// ---------------------------------------------------------------------------
__global__ void __launch_bounds__(256)
qk_tf32(const float* __restrict__ qkv, float* __restrict__ sc)
{
    __shared__ float As[32][132];   // [d][q]
    __shared__ float Bs[32][132];   // [d][k_tok]

    const int tid  = threadIdx.x;
    const int warp = tid >> 5, lane = tid & 31;
    const int grp  = lane >> 2, qd = lane & 3;
    const int wm   = (warp >> 2) * 64;
    const int wn   = (warp & 3)  * 32;

    const int bh = blockIdx.z;
    const int b = bh / H_, h = bh % H_;
    const float* Qb = qkv + (long)b * S_ * D3_ + h * HD_        + (long)blockIdx.y * 128 * D3_;
    const float* Kb = qkv + (long)b * S_ * D3_ + D_ + h * HD_   + (long)blockIdx.x * 128 * D3_;

    const int am = tid >> 1;
    const int ak = (tid & 1) * 4;

    float acc[4][4][4] = {};

    for (int k0 = 0; k0 < HD_; k0 += 32) {
        const float* pa = Qb + (long)am * D3_ + k0 + ak;
        const float* pb = Kb + (long)am * D3_ + k0 + ak;
#pragma unroll
        for (int kk = 0; kk < 32; kk += 8) {
            float4 va = *(const float4*)(pa + kk);
            As[ak + kk + 0][am] = to_tf32(va.x);
            As[ak + kk + 1][am] = to_tf32(va.y);
            As[ak + kk + 2][am] = to_tf32(va.z);
            As[ak + kk + 3][am] = to_tf32(va.w);
            float4 vb = *(const float4*)(pb + kk);
            Bs[ak + kk + 0][am] = to_tf32(vb.x);
            Bs[ak + kk + 1][am] = to_tf32(vb.y);
            Bs[ak + kk + 2][am] = to_tf32(vb.z);
            Bs[ak + kk + 3][am] = to_tf32(vb.w);
        }
        __syncthreads();

#pragma unroll
        for (int ks = 0; ks < 4; ks++) {
            const int kb = ks * 8;
            uint32_t a[4][4], b2[4][2];
#pragma unroll
            for (int i = 0; i < 4; i++) {
                int m = wm + i * 16 + grp;
                a[i][0] = __float_as_uint(As[kb + qd    ][m]);
                a[i][1] = __float_as_uint(As[kb + qd    ][m + 8]);
                a[i][2] = __float_as_uint(As[kb + qd + 4][m]);
                a[i][3] = __float_as_uint(As[kb + qd + 4][m + 8]);
            }
#pragma unroll
            for (int j = 0; j < 4; j++) {
                int n = wn + j * 8 + grp;
                b2[j][0] = __float_as_uint(Bs[kb + qd    ][n]);
                b2[j][1] = __float_as_uint(Bs[kb + qd + 4][n]);
            }
#pragma unroll
            for (int i = 0; i < 4; i++)
#pragma unroll
                for (int j = 0; j < 4; j++)
                    mma8(acc[i][j], a[i], b2[j]);
        }
        __syncthreads();
    }

    float* Cb = sc + (long)bh * S_ * S_;
    const int row0 = blockIdx.y * 128 + wm + grp;
    const int col0 = blockIdx.x * 128 + wn + qd * 2;
#pragma unroll
    for (int i = 0; i < 4; i++)
#pragma unroll
        for (int j = 0; j < 4; j++) {
            int r  = row0 + i * 16;
            int cc = col0 + j * 8;
            *(float2*)(Cb + (long)r * S_ + cc) =
                make_float2(acc[i][j][0] * 0.125f, acc[i][j][1] * 0.125f);
            *(float2*)(Cb + (long)(r + 8) * S_ + cc) =
                make_float2(acc[i][j][2] * 0.125f, acc[i][j][3] * 0.125f);
        }
}

// ---------------------------------------------------------------------------
// 4) Row softmax + clip(1e-6, 1.0), in-place, row length 1024
// ---------------------------------------------------------------------------
__global__ void __launch_bounds__(256)
softmax_clamp_kernel(float* __restrict__ sc)
{
    float* p = sc + (long)blockIdx.x * S_;
    int tid = threadIdx.x, wid = tid >> 5, lane = tid & 31;
    __shared__ float sred[8];
    __shared__ float sbc[2];

    float4 v = ((float4*)p)[tid];
    float m = fmaxf(fmaxf(v.x, v.y), fmaxf(v.z, v.w));
    m = warp_max(m);
    if (lane == 0) sred[wid] = m;
    __syncthreads();
    if (wid == 0) {
        float t = (lane < 8) ? sred[lane] : -INFINITY;
        t = warp_max(t);
        if (lane == 0) sbc[0] = t;
    }
    __syncthreads();
    float rowmax = sbc[0];

    float4 e;
    e.x = expf(v.x - rowmax);
    e.y = expf(v.y - rowmax);
    e.z = expf(v.z - rowmax);
    e.w = expf(v.w - rowmax);
    float s = e.x + e.y + e.z + e.w;
    s = warp_sum(s);
    if (lane == 0) sred[wid] = s;
    __syncthreads();
    if (wid == 0) {
        float t = (lane < 8) ? sred[lane] : 0.0f;
        t = warp_sum(t);
        if (lane == 0) sbc[1] = t;
    }
    __syncthreads();
    float inv = 1.0f / sbc[1];

    e.x = fminf(fmaxf(e.x * inv, 1e-6f), 1.0f);
    e.y = fminf(fmaxf(e.y * inv, 1e-6f), 1.0f);
    e.z = fminf(fmaxf(e.z * inv, 1e-6f), 1.0f);
    e.w = fminf(fmaxf(e.w * inv, 1e-6f), 1.0f);
    ((float4*)p)[tid] = e;
}

// ---------------------------------------------------------------------------
// 5) PV: attn[b, s, h*64+d] = sum_k W[bh,s,k] * V[bh,k,d]
//    TF32 mma, CTA tile 128x64x32, warp tile 32x32 (4x2 warps).
//    V read directly from fused qkv; output written in (B,S,D) layout.
// ---------------------------------------------------------------------------
__global__ void __launch_bounds__(256)
pv_tf32(const float* __restrict__ sc, const float* __restrict__ qkv,
        float* __restrict__ attn)
{
    __shared__ float As[32][132];   // [k][s]
    __shared__ float Bs[32][68];    // [k][d]

    const int tid  = threadIdx.x;
    const int warp = tid >> 5, lane = tid & 31;
    const int grp  = lane >> 2, qd = lane & 3;
    const int wm   = (warp >> 1) * 32;  // 0,32,64,96
    const int wn   = (warp & 1)  * 32;  // 0,32

    const int bh = blockIdx.z;
    const int b = bh / H_, h = bh % H_;
    const float* Ab = sc  + (long)bh * S_ * S_ + (long)blockIdx.y * 128 * S_;
    const float* Vb = qkv + (long)b * S_ * D3_ + 2 * D_ + h * HD_;
    float*       Cb = attn + (long)b * S_ * D_ + h * HD_ + (long)blockIdx.y * 128 * D_;

    const int am = tid >> 1;
    const int ak = (tid & 1) * 4;
    const int bk = tid >> 4;            // 0..15
    const int bn = (tid & 15) * 4;      // 0..60

    float acc[2][4][4] = {};

    for (int k0 = 0; k0 < S_; k0 += 32) {
        const float* pa = Ab + (long)am * S_ + k0 + ak;
#pragma unroll
        for (int kk = 0; kk < 32; kk += 8) {
            float4 v = *(const float4*)(pa + kk);
            As[ak + kk + 0][am] = to_tf32(v.x);
            As[ak + kk + 1][am] = to_tf32(v.y);
            As[ak + kk + 2][am] = to_tf32(v.z);
            As[ak + kk + 3][am] = to_tf32(v.w);
        }
#pragma unroll
        for (int kk = 0; kk < 32; kk += 16) {
            float4 v = *(const float4*)(Vb + (long)(k0 + bk + kk) * D3_ + bn);
            v.x = to_tf32(v.x); v.y = to_tf32(v.y);
            v.z = to_tf32(v.z); v.w = to_tf32(v.w);
            *(float4*)(&Bs[bk + kk][bn]) = v;
        }
        __syncthreads();

#pragma unroll
        for (int ks = 0; ks < 4; ks++) {
            const int kb = ks * 8;
            uint32_t a[2][4], b2[4][2];
#pragma unroll
            for (int i = 0; i < 2; i++) {
                int m = wm + i * 16 + grp;
                a[i][0] = __float_as_uint(As[kb + qd    ][m]);
                a[i][1] = __float_as_uint(As[kb + qd    ][m + 8]);
                a[i][2] = __float_as_uint(As[kb + qd + 4][m]);
                a[i][3] = __float_as_uint(As[kb + qd + 4][m + 8]);
            }
#pragma unroll
            for (int j = 0; j < 4; j++) {
                int n = wn + j * 8 + grp;
                b2[j][0] = __float_as_uint(Bs[kb + qd    ][n]);
                b2[j][1] = __float_as_uint(Bs[kb + qd + 4][n]);
            }
#pragma unroll
            for (int i = 0; i < 2; i++)
#pragma unroll
                for (int j = 0; j < 4; j++)
                    mma8(acc[i][j], a[i], b2[j]);
        }
        __syncthreads();
    }

    const int row0 = wm + grp;
    const int col0 = wn + qd * 2;
#pragma unroll
    for (int i = 0; i < 2; i++)
#pragma unroll
        for (int j = 0; j < 4; j++) {
            int r  = row0 + i * 16;
            int cc = col0 + j * 8;
            *(float2*)(Cb + (long)r * D_ + cc) =
                make_float2(acc[i][j][0], acc[i][j][1]);
            *(float2*)(Cb + (long)(r + 8) * D_ + cc) =
                make_float2(acc[i][j][2], acc[i][j][3]);
        }
}

// ---------------------------------------------------------------------------
// 6) LayerNorm (row length 768)
// ---------------------------------------------------------------------------
__global__ void __launch_bounds__(256)
layernorm_kernel(const float* __restrict__ in, const float* __restrict__ g,
                 const float* __restrict__ bb, float* __restrict__ out)
{
    const float* p = in + (long)blockIdx.x * D_;
    float* o = out + (long)blockIdx.x * D_;
    int tid = threadIdx.x, wid = tid >> 5, lane = tid & 31;

    float x0 = p[tid], x1 = p[tid + 256], x2 = p[tid + 512];
    float s  = x0 + x1 + x2;
    float s2 = x0 * x0 + x1 * x1 + x2 * x2;
    s  = warp_sum(s);
    s2 = warp_sum(s2);

    __shared__ float red[16];
    if (lane == 0) { red[wid] = s; red[8 + wid] = s2; }
    __syncthreads();
    if (tid == 0) {
        float a = 0.f, b2 = 0.f;
#pragma unroll
        for (int i = 0; i < 8; i++) { a += red[i]; b2 += red[8 + i]; }
        red[0] = a; red[8] = b2;
    }
    __syncthreads();
    float mu  = red[0] * (1.0f / (float)D_);
    float var = red[8] * (1.0f / (float)D_) - mu * mu;
    float inv = rsqrtf(var + 1e-5f);

    o[tid]       = (x0 - mu) * inv * g[tid]       + bb[tid];
    o[tid + 256] = (x1 - mu) * inv * g[tid + 256] + bb[tid + 256];
    o[tid + 512] = (x2 - mu) * inv * g[tid + 512] + bb[tid + 512];
}

// ---------------------------------------------------------------------------
// Orchestration
// ---------------------------------------------------------------------------
extern "C" void kernel_launch(void* const* d_in, const int* in_sizes, int n_in,
                              void* d_out, int out_size)
{
    (void)in_sizes; (void)n_in; (void)out_size;

    const float* x    = (const float*)d_in[0];
    const float* Wqkv = (const float*)d_in[1];
    const float* bqkv = (const float*)d_in[2];
    const float* Wo   = (const float*)d_in[3];
    const float* bo   = (const float*)d_in[4];
    const float* ln1g = (const float*)d_in[5];
    const float* ln1b = (const float*)d_in[6];
    const float* W1   = (const float*)d_in[7];
    const float* b1   = (const float*)d_in[8];
    const float* W2   = (const float*)d_in[9];
    const float* b2   = (const float*)d_in[10];
    const float* ln2g = (const float*)d_in[11];
    const float* ln2b = (const float*)d_in[12];
    const float* lnfg = (const float*)d_in[13];
    const float* lnfb = (const float*)d_in[14];

    float *p_h, *p_tmp, *p_attn, *p_qkv, *p_sc, *p_ffn;
    cudaGetSymbolAddress((void**)&p_h,    g_h);
    cudaGetSymbolAddress((void**)&p_tmp,  g_tmp);
    cudaGetSymbolAddress((void**)&p_attn, g_attn);
    cudaGetSymbolAddress((void**)&p_qkv,  g_qkv);
    cudaGetSymbolAddress((void**)&p_sc,   g_sc);
    cudaGetSymbolAddress((void**)&p_ffn,  g_ffn);

    const int elems = MTOK * D_;

    pos_add_kernel<<<elems / 256, 256>>>(x, p_h);

    for (int l = 0; l < L_; l++) {
        const float* wqkv = Wqkv + (size_t)l * D_ * D3_;
        const float* bq   = bqkv + (size_t)l * D3_;
        const float* wo   = Wo   + (size_t)l * D_ * D_;
        const float* bol  = bo   + (size_t)l * D_;
        const float* w1   = W1   + (size_t)l * D_ * F_;
        const float* b1l  = b1   + (size_t)l * F_;
        const float* w2   = W2   + (size_t)l * F_ * D_;
        const float* b2l  = b2   + (size_t)l * D_;

        // qkv = h @ Wqkv + bqkv              (4096 x 2304 x 768)
        gemm_tf32<false, false><<<dim3(D3_ / 128, MTOK / 128), 256>>>(
            p_h, wqkv, bq, nullptr, p_qkv, D_, D3_);

        // scores = 0.125 * Q @ K^T           (batched 1024 x 1024 x 64)
        qk_tf32<<<dim3(S_ / 128, S_ / 128, BH_), 256>>>(p_qkv, p_sc);

        // softmax + clamp
        softmax_clamp_kernel<<<BH_ * S_, 256>>>(p_sc);

        // attn = W @ V                       (batched 1024 x 64 x 1024)
        pv_tf32<<<dim3(1, S_ / 128, BH_), 256>>>(p_sc, p_qkv, p_attn);

        // tmp = attn @ Wo + bo + h           (4096 x 768 x 768)
        gemm_tf32<false, true><<<dim3(D_ / 128, MTOK / 128), 256>>>(
            p_attn, wo, bol, p_h, p_tmp, D_, D_);

        layernorm_kernel<<<MTOK, 256>>>(p_tmp, ln1g + (size_t)l * D_,
                                        ln1b + (size_t)l * D_, p_h);

        // ffn = relu(h @ W1 + b1)            (4096 x 3072 x 768)
        gemm_tf32<true, false><<<dim3(F_ / 128, MTOK / 128), 256>>>(
            p_h, w1, b1l, nullptr, p_ffn, D_, F_);

        // tmp = ffn @ W2 + b2 + h            (4096 x 768 x 3072)
        gemm_tf32<false, true><<<dim3(D_ / 128, MTOK / 128), 256>>>(
            p_ffn, w2, b2l, p_h, p_tmp, F_, D_);

        layernorm_kernel<<<MTOK, 256>>>(p_tmp, ln2g + (size_t)l * D_,
                                        ln2b + (size_t)l * D_, p_h);
    }

    layernorm_kernel<<<MTOK, 256>>>(p_h, lnfg, lnfb, (float*)d_out);
}

// round 12
// speedup vs baseline: 1.0051x; 1.0033x over previous
#include <cuda_runtime.h>
#include <math.h>
#include <stdint.h>

// Problem constants (fixed by setup_inputs)
#define B_   4
#define S_   1024
#define D_   768
#define H_   12
#define HD_  64
#define F_   3072
#define L_   6
#define D3_  2304
#define BH_  (B_ * H_)
#define MTOK (B_ * S_)   // 4096 token rows

// ---------------------------------------------------------------------------
// Scratch (static device globals; no allocation anywhere)
// ---------------------------------------------------------------------------
__device__ float g_h   [(size_t)MTOK * D_];     // hidden state
__device__ float g_tmp [(size_t)MTOK * D_];     // pre-LN sums
__device__ float g_attn[(size_t)MTOK * D_];     // attention output (B,S,D)
__device__ float g_qkv [(size_t)MTOK * D3_];    // fused qkv (q|k|v per token)
__device__ float g_sc  [(size_t)BH_ * S_ * S_]; // scores / weights
__device__ float g_ffn [(size_t)MTOK * F_];     // FFN intermediate

// ---------------------------------------------------------------------------
// Helpers
// ---------------------------------------------------------------------------
__device__ __forceinline__ float to_tf32(float x) {
    uint32_t u;
    asm("cvt.rna.tf32.f32 %0, %1;" : "=r"(u) : "f"(x));
    return __uint_as_float(u);
}

// D += A(16x8, tf32, row) * B(8x8, tf32, col)
__device__ __forceinline__ void mma8(float* c, const uint32_t* a, const uint32_t* b) {
    asm volatile(
        "mma.sync.aligned.m16n8k8.row.col.f32.tf32.tf32.f32 "
        "{%0,%1,%2,%3}, {%4,%5,%6,%7}, {%8,%9}, {%0,%1,%2,%3};\n"
        : "+f"(c[0]), "+f"(c[1]), "+f"(c[2]), "+f"(c[3])
        : "r"(a[0]), "r"(a[1]), "r"(a[2]), "r"(a[3]), "r"(b[0]), "r"(b[1]));
}

__device__ __forceinline__ float warp_max(float v) {
#pragma unroll
    for (int o = 16; o > 0; o >>= 1) v = fmaxf(v, __shfl_xor_sync(0xffffffffu, v, o));
    return v;
}
__device__ __forceinline__ float warp_sum(float v) {
#pragma unroll
    for (int o = 16; o > 0; o >>= 1) v += __shfl_xor_sync(0xffffffffu, v, o);
    return v;
}

// ---------------------------------------------------------------------------
// 1) x + positional encoding
// ---------------------------------------------------------------------------
__global__ void pos_add_kernel(const float* __restrict__ x, float* __restrict__ out) {
    int t = blockIdx.x * blockDim.x + threadIdx.x;
    if (t >= MTOK * D_) return;
    int d = t % D_;
    int s = (t / D_) % S_;
    int i2 = d & ~1;
    float f = expf((float)i2 * (-9.210340371976184f / (float)D_)); // -log(1e4)/D
    float ang = (float)s * f;
    float pe = (d & 1) ? cosf(ang) : sinf(ang);
    out[t] = x[t] + pe;
}

// ---------------------------------------------------------------------------
// 2) Dense TF32 tensor-core GEMM: C = A[M,K] @ B[K,N] (+bias)(+relu)(+resid)
//    CTA tile 128x128x32, 8 warps (2x4), warp tile 64x32, m16n8k8 tf32 mma.
// ---------------------------------------------------------------------------
template<bool RELU, bool RESID>
__global__ void __launch_bounds__(256)
gemm_tf32(const float* __restrict__ A, const float* __restrict__ Bm,
          const float* __restrict__ bias, const float* __restrict__ R,
          float* __restrict__ C, int K, int N)
{
    __shared__ float As[32][132];   // [k][m], stride 132 => conflict-free frags
    __shared__ float Bs[32][132];   // [k][n]

    const int tid  = threadIdx.x;
    const int warp = tid >> 5, lane = tid & 31;
    const int grp  = lane >> 2, qd = lane & 3;
    const int wm   = (warp >> 2) * 64;   // 0 / 64
    const int wn   = (warp & 3)  * 32;   // 0..96

    const float* Ab = A  + (long)blockIdx.y * 128 * K;
    const float* Bb = Bm + blockIdx.x * 128;

    const int am = tid >> 1;            // 0..127
    const int ak = (tid & 1) * 4;       // 0 / 4
    const int bk = tid >> 5;            // 0..7
    const int bn = (tid & 31) * 4;      // 0..124

    float acc[4][4][4] = {};

    for (int k0 = 0; k0 < K; k0 += 32) {
        const float* pa = Ab + (long)am * K + k0 + ak;
#pragma unroll
        for (int kk = 0; kk < 32; kk += 8) {
            float4 v = *(const float4*)(pa + kk);
            As[ak + kk + 0][am] = to_tf32(v.x);
            As[ak + kk + 1][am] = to_tf32(v.y);
            As[ak + kk + 2][am] = to_tf32(v.z);
            As[ak + kk + 3][am] = to_tf32(v.w);
        }
#pragma unroll
        for (int kk = 0; kk < 32; kk += 8) {
            float4 v = *(const float4*)(Bb + (long)(k0 + bk + kk) * N + bn);
            v.x = to_tf32(v.x); v.y = to_tf32(v.y);
            v.z = to_tf32(v.z); v.w = to_tf32(v.w);
            *(float4*)(&Bs[bk + kk][bn]) = v;
        }
        __syncthreads();

#pragma unroll
        for (int ks = 0; ks < 4; ks++) {
            const int kb = ks * 8;
            uint32_t a[4][4], b[4][2];
#pragma unroll
            for (int i = 0; i < 4; i++) {
                int m = wm + i * 16 + grp;
                a[i][0] = __float_as_uint(As[kb + qd    ][m]);
                a[i][1] = __float_as_uint(As[kb + qd    ][m + 8]);
                a[i][2] = __float_as_uint(As[kb + qd + 4][m]);
                a[i][3] = __float_as_uint(As[kb + qd + 4][m + 8]);
            }
#pragma unroll
            for (int j = 0; j < 4; j++) {
                int n = wn + j * 8 + grp;
                b[j][0] = __float_as_uint(Bs[kb + qd    ][n]);
                b[j][1] = __float_as_uint(Bs[kb + qd + 4][n]);
            }
#pragma unroll
            for (int i = 0; i < 4; i++)
#pragma unroll
                for (int j = 0; j < 4; j++)
                    mma8(acc[i][j], a[i], b[j]);
        }
        __syncthreads();
    }

    const int row0 = blockIdx.y * 128 + wm + grp;
    const int col0 = blockIdx.x * 128 + wn + qd * 2;
#pragma unroll
    for (int i = 0; i < 4; i++) {
#pragma unroll
        for (int j = 0; j < 4; j++) {
            int r  = row0 + i * 16;
            int cc = col0 + j * 8;
            float2 v0 = make_float2(acc[i][j][0], acc[i][j][1]);
            float2 v1 = make_float2(acc[i][j][2], acc[i][j][3]);
            if (bias) {
                float b0 = bias[cc], b1 = bias[cc + 1];
                v0.x += b0; v0.y += b1; v1.x += b0; v1.y += b1;
            }
            if (RELU) {
                v0.x = fmaxf(v0.x, 0.f); v0.y = fmaxf(v0.y, 0.f);
                v1.x = fmaxf(v1.x, 0.f); v1.y = fmaxf(v1.y, 0.f);
            }
            long o0 = (long)r * N + cc;
            long o1 = (long)(r + 8) * N + cc;
            if (RESID) {
                float2 r0 = *(const float2*)(R + o0);
                float2 r1 = *(const float2*)(R + o1);
                v0.x += r0.x; v0.y += r0.y; v1.x += r1.x; v1.y += r1.y;
            }
            *(float2*)(C + o0) = v0;
            *(float2*)(C + o1) = v1;
        }
    }
}

// ---------------------------------------------------------------------------
// 3) QK^T: scores[bh, q, k] = 0.125 * sum_d Q[q][d] K[k][d]
//    Q, K read directly out of fused qkv (K is naturally col-major for row.col).
// ---------------------------------------------------------------------------
__global__ void __launch_bounds__(256)
qk_tf32(const float* __restrict__ qkv, float* __restrict__ sc)
{
    __shared__ float As[32][132];   // [d][q]
    __shared__ float Bs[32][132];   // [d][k_tok]

    const int tid  = threadIdx.x;
    const int warp = tid >> 5, lane = tid & 31;
    const int grp  = lane >> 2, qd = lane & 3;
    const int wm   = (warp >> 2) * 64;
    const int wn   = (warp & 3)  * 32;

    const int bh = blockIdx.z;
    const int b = bh / H_, h = bh % H_;
    const float* Qb = qkv + (long)b * S_ * D3_ + h * HD_        + (long)blockIdx.y * 128 * D3_;
    const float* Kb = qkv + (long)b * S_ * D3_ + D_ + h * HD_   + (long)blockIdx.x * 128 * D3_;

    const int am = tid >> 1;
    const int ak = (tid & 1) * 4;

    float acc[4][4][4] = {};

    for (int k0 = 0; k0 < HD_; k0 += 32) {
        const float* pa = Qb + (long)am * D3_ + k0 + ak;
        const float* pb = Kb + (long)am * D3_ + k0 + ak;
#pragma unroll
        for (int kk = 0; kk < 32; kk += 8) {
            float4 va = *(const float4*)(pa + kk);
            As[ak + kk + 0][am] = to_tf32(va.x);
            As[ak + kk + 1][am] = to_tf32(va.y);
            As[ak + kk + 2][am] = to_tf32(va.z);
            As[ak + kk + 3][am] = to_tf32(va.w);
            float4 vb = *(const float4*)(pb + kk);
            Bs[ak + kk + 0][am] = to_tf32(vb.x);
            Bs[ak + kk + 1][am] = to_tf32(vb.y);
            Bs[ak + kk + 2][am] = to_tf32(vb.z);
            Bs[ak + kk + 3][am] = to_tf32(vb.w);
        }
        __syncthreads();

#pragma unroll
        for (int ks = 0; ks < 4; ks++) {
            const int kb = ks * 8;
            uint32_t a[4][4], b2[4][2];
#pragma unroll
            for (int i = 0; i < 4; i++) {
                int m = wm + i * 16 + grp;
                a[i][0] = __float_as_uint(As[kb + qd    ][m]);
                a[i][1] = __float_as_uint(As[kb + qd    ][m + 8]);
                a[i][2] = __float_as_uint(As[kb + qd + 4][m]);
                a[i][3] = __float_as_uint(As[kb + qd + 4][m + 8]);
            }
#pragma unroll
            for (int j = 0; j < 4; j++) {
                int n = wn + j * 8 + grp;
                b2[j][0] = __float_as_uint(Bs[kb + qd    ][n]);
                b2[j][1] = __float_as_uint(Bs[kb + qd + 4][n]);
            }
#pragma unroll
            for (int i = 0; i < 4; i++)
#pragma unroll
                for (int j = 0; j < 4; j++)
                    mma8(acc[i][j], a[i], b2[j]);
        }
        __syncthreads();
    }

    float* Cb = sc + (long)bh * S_ * S_;
    const int row0 = blockIdx.y * 128 + wm + grp;
    const int col0 = blockIdx.x * 128 + wn + qd * 2;
#pragma unroll
    for (int i = 0; i < 4; i++)
#pragma unroll
        for (int j = 0; j < 4; j++) {
            int r  = row0 + i * 16;
            int cc = col0 + j * 8;
            *(float2*)(Cb + (long)r * S_ + cc) =
                make_float2(acc[i][j][0] * 0.125f, acc[i][j][1] * 0.125f);
            *(float2*)(Cb + (long)(r + 8) * S_ + cc) =
                make_float2(acc[i][j][2] * 0.125f, acc[i][j][3] * 0.125f);
        }
}

// ---------------------------------------------------------------------------
// 4) Row softmax + clip(1e-6, 1.0), in-place, row length 1024
// ---------------------------------------------------------------------------
__global__ void __launch_bounds__(256)
softmax_clamp_kernel(float* __restrict__ sc)
{
    float* p = sc + (long)blockIdx.x * S_;
    int tid = threadIdx.x, wid = tid >> 5, lane = tid & 31;
    __shared__ float sred[8];
    __shared__ float sbc[2];

    float4 v = ((float4*)p)[tid];
    float m = fmaxf(fmaxf(v.x, v.y), fmaxf(v.z, v.w));
    m = warp_max(m);
    if (lane == 0) sred[wid] = m;
    __syncthreads();
    if (wid == 0) {
        float t = (lane < 8) ? sred[lane] : -INFINITY;
        t = warp_max(t);
        if (lane == 0) sbc[0] = t;
    }
    __syncthreads();
    float rowmax = sbc[0];

    float4 e;
    e.x = expf(v.x - rowmax);
    e.y = expf(v.y - rowmax);
    e.z = expf(v.z - rowmax);
    e.w = expf(v.w - rowmax);
    float s = e.x + e.y + e.z + e.w;
    s = warp_sum(s);
    if (lane == 0) sred[wid] = s;
    __syncthreads();
    if (wid == 0) {
        float t = (lane < 8) ? sred[lane] : 0.0f;
        t = warp_sum(t);
        if (lane == 0) sbc[1] = t;
    }
    __syncthreads();
    float inv = 1.0f / sbc[1];

    e.x = fminf(fmaxf(e.x * inv, 1e-6f), 1.0f);
    e.y = fminf(fmaxf(e.y * inv, 1e-6f), 1.0f);
    e.z = fminf(fmaxf(e.z * inv, 1e-6f), 1.0f);
    e.w = fminf(fmaxf(e.w * inv, 1e-6f), 1.0f);
    ((float4*)p)[tid] = e;
}

// ---------------------------------------------------------------------------
// 5) PV: attn[b, s, h*64+d] = sum_k W[bh,s,k] * V[bh,k,d]
//    TF32 mma, CTA tile 128x64x32, warp tile 32x32 (4x2 warps).
//    V read directly from fused qkv; output written in (B,S,D) layout.
// ---------------------------------------------------------------------------
__global__ void __launch_bounds__(256)
pv_tf32(const float* __restrict__ sc, const float* __restrict__ qkv,
        float* __restrict__ attn)
{
    __shared__ float As[32][132];   // [k][s]
    __shared__ float Bs[32][68];    // [k][d]

    const int tid  = threadIdx.x;
    const int warp = tid >> 5, lane = tid & 31;
    const int grp  = lane >> 2, qd = lane & 3;
    const int wm   = (warp >> 1) * 32;  // 0,32,64,96
    const int wn   = (warp & 1)  * 32;  // 0,32

    const int bh = blockIdx.z;
    const int b = bh / H_, h = bh % H_;
    const float* Ab = sc  + (long)bh * S_ * S_ + (long)blockIdx.y * 128 * S_;
    const float* Vb = qkv + (long)b * S_ * D3_ + 2 * D_ + h * HD_;
    float*       Cb = attn + (long)b * S_ * D_ + h * HD_ + (long)blockIdx.y * 128 * D_;

    const int am = tid >> 1;
    const int ak = (tid & 1) * 4;
    const int bk = tid >> 4;            // 0..15
    const int bn = (tid & 15) * 4;      // 0..60

    float acc[2][4][4] = {};

    for (int k0 = 0; k0 < S_; k0 += 32) {
        const float* pa = Ab + (long)am * S_ + k0 + ak;
#pragma unroll
        for (int kk = 0; kk < 32; kk += 8) {
            float4 v = *(const float4*)(pa + kk);
            As[ak + kk + 0][am] = to_tf32(v.x);
            As[ak + kk + 1][am] = to_tf32(v.y);
            As[ak + kk + 2][am] = to_tf32(v.z);
            As[ak + kk + 3][am] = to_tf32(v.w);
        }
#pragma unroll
        for (int kk = 0; kk < 32; kk += 16) {
            float4 v = *(const float4*)(Vb + (long)(k0 + bk + kk) * D3_ + bn);
            v.x = to_tf32(v.x); v.y = to_tf32(v.y);
            v.z = to_tf32(v.z); v.w = to_tf32(v.w);
            *(float4*)(&Bs[bk + kk][bn]) = v;
        }
        __syncthreads();

#pragma unroll
        for (int ks = 0; ks < 4; ks++) {
            const int kb = ks * 8;
            uint32_t a[2][4], b2[4][2];
#pragma unroll
            for (int i = 0; i < 2; i++) {
                int m = wm + i * 16 + grp;
                a[i][0] = __float_as_uint(As[kb + qd    ][m]);
                a[i][1] = __float_as_uint(As[kb + qd    ][m + 8]);
                a[i][2] = __float_as_uint(As[kb + qd + 4][m]);
                a[i][3] = __float_as_uint(As[kb + qd + 4][m + 8]);
            }
#pragma unroll
            for (int j = 0; j < 4; j++) {
                int n = wn + j * 8 + grp;
                b2[j][0] = __float_as_uint(Bs[kb + qd    ][n]);
                b2[j][1] = __float_as_uint(Bs[kb + qd + 4][n]);
            }
#pragma unroll
            for (int i = 0; i < 2; i++)
#pragma unroll
                for (int j = 0; j < 4; j++)
                    mma8(acc[i][j], a[i], b2[j]);
        }
        __syncthreads();
    }

    const int row0 = wm + grp;
    const int col0 = wn + qd * 2;
#pragma unroll
    for (int i = 0; i < 2; i++)
#pragma unroll
        for (int j = 0; j < 4; j++) {
            int r  = row0 + i * 16;
            int cc = col0 + j * 8;
            *(float2*)(Cb + (long)r * D_ + cc) =
                make_float2(acc[i][j][0], acc[i][j][1]);
            *(float2*)(Cb + (long)(r + 8) * D_ + cc) =
                make_float2(acc[i][j][2], acc[i][j][3]);
        }
}

// ---------------------------------------------------------------------------
// 6) LayerNorm (row length 768)
// ---------------------------------------------------------------------------
__global__ void __launch_bounds__(256)
layernorm_kernel(const float* __restrict__ in, const float* __restrict__ g,
                 const float* __restrict__ bb, float* __restrict__ out)
{
    const float* p = in + (long)blockIdx.x * D_;
    float* o = out + (long)blockIdx.x * D_;
    int tid = threadIdx.x, wid = tid >> 5, lane = tid & 31;

    float x0 = p[tid], x1 = p[tid + 256], x2 = p[tid + 512];
    float s  = x0 + x1 + x2;
    float s2 = x0 * x0 + x1 * x1 + x2 * x2;
    s  = warp_sum(s);
    s2 = warp_sum(s2);

    __shared__ float red[16];
    if (lane == 0) { red[wid] = s; red[8 + wid] = s2; }
    __syncthreads();
    if (tid == 0) {
        float a = 0.f, b2 = 0.f;
#pragma unroll
        for (int i = 0; i < 8; i++) { a += red[i]; b2 += red[8 + i]; }
        red[0] = a; red[8] = b2;
    }
    __syncthreads();
    float mu  = red[0] * (1.0f / (float)D_);
    float var = red[8] * (1.0f / (float)D_) - mu * mu;
    float inv = rsqrtf(var + 1e-5f);

    o[tid]       = (x0 - mu) * inv * g[tid]       + bb[tid];
    o[tid + 256] = (x1 - mu) * inv * g[tid + 256] + bb[tid + 256];
    o[tid + 512] = (x2 - mu) * inv * g[tid + 512] + bb[tid + 512];
}

// ---------------------------------------------------------------------------
// Orchestration
// ---------------------------------------------------------------------------
extern "C" void kernel_launch(void* const* d_in, const int* in_sizes, int n_in,
                              void* d_out, int out_size)
{
    (void)in_sizes; (void)n_in; (void)out_size;

    const float* x    = (const float*)d_in[0];
    const float* Wqkv = (const float*)d_in[1];
    const float* bqkv = (const float*)d_in[2];
    const float* Wo   = (const float*)d_in[3];
    const float* bo   = (const float*)d_in[4];
    const float* ln1g = (const float*)d_in[5];
    const float* ln1b = (const float*)d_in[6];
    const float* W1   = (const float*)d_in[7];
    const float* b1   = (const float*)d_in[8];
    const float* W2   = (const float*)d_in[9];
    const float* b2   = (const float*)d_in[10];
    const float* ln2g = (const float*)d_in[11];
    const float* ln2b = (const float*)d_in[12];
    const float* lnfg = (const float*)d_in[13];
    const float* lnfb = (const float*)d_in[14];

    float *p_h, *p_tmp, *p_attn, *p_qkv, *p_sc, *p_ffn;
    cudaGetSymbolAddress((void**)&p_h,    g_h);
    cudaGetSymbolAddress((void**)&p_tmp,  g_tmp);
    cudaGetSymbolAddress((void**)&p_attn, g_attn);
    cudaGetSymbolAddress((void**)&p_qkv,  g_qkv);
    cudaGetSymbolAddress((void**)&p_sc,   g_sc);
    cudaGetSymbolAddress((void**)&p_ffn,  g_ffn);

    const int elems = MTOK * D_;

    pos_add_kernel<<<elems / 256, 256>>>(x, p_h);

    for (int l = 0; l < L_; l++) {
        const float* wqkv = Wqkv + (size_t)l * D_ * D3_;
        const float* bq   = bqkv + (size_t)l * D3_;
        const float* wo   = Wo   + (size_t)l * D_ * D_;
        const float* bol  = bo   + (size_t)l * D_;
        const float* w1   = W1   + (size_t)l * D_ * F_;
        const float* b1l  = b1   + (size_t)l * F_;
        const float* w2   = W2   + (size_t)l * F_ * D_;
        const float* b2l  = b2   + (size_t)l * D_;

        // qkv = h @ Wqkv + bqkv              (4096 x 2304 x 768)
        gemm_tf32<false, false><<<dim3(D3_ / 128, MTOK / 128), 256>>>(
            p_h, wqkv, bq, nullptr, p_qkv, D_, D3_);

        // scores = 0.125 * Q @ K^T           (batched 1024 x 1024 x 64)
        qk_tf32<<<dim3(S_ / 128, S_ / 128, BH_), 256>>>(p_qkv, p_sc);

        // softmax + clamp
        softmax_clamp_kernel<<<BH_ * S_, 256>>>(p_sc);

        // attn = W @ V                       (batched 1024 x 64 x 1024)
        pv_tf32<<<dim3(1, S_ / 128, BH_), 256>>>(p_sc, p_qkv, p_attn);

        // tmp = attn @ Wo + bo + h           (4096 x 768 x 768)
        gemm_tf32<false, true><<<dim3(D_ / 128, MTOK / 128), 256>>>(
            p_attn, wo, bol, p_h, p_tmp, D_, D_);

        layernorm_kernel<<<MTOK, 256>>>(p_tmp, ln1g + (size_t)l * D_,
                                        ln1b + (size_t)l * D_, p_h);

        // ffn = relu(h @ W1 + b1)            (4096 x 3072 x 768)
        gemm_tf32<true, false><<<dim3(F_ / 128, MTOK / 128), 256>>>(
            p_h, w1, b1l, nullptr, p_ffn, D_, F_);

        // tmp = ffn @ W2 + b2 + h            (4096 x 768 x 3072)
        gemm_tf32<false, true><<<dim3(D_ / 128, MTOK / 128), 256>>>(
            p_ffn, w2, b2l, p_h, p_tmp, F_, D_);

        layernorm_kernel<<<MTOK, 256>>>(p_tmp, ln2g + (size_t)l * D_,
                                        ln2b + (size_t)l * D_, p_h);
    }

    layernorm_kernel<<<MTOK, 256>>>(p_h, lnfg, lnfb, (float*)d_out);
}